// round 7
// baseline (speedup 1.0000x reference)
#include <cuda_runtime.h>
#include <cuda_bf16.h>
#include <cstdint>

// ESN reservoir: B=256, T=4096, D=8, U=64, leaky=1.0
// state_t = tanh(x_proj_t + state_{t-1} @ W_rec), W_rec ~64 nnz total.
//
// State carried as r = rcp(exp(2z)+1)  (n = tanh(z) = 1 - 2r).
// Recurrent sum rewritten:  sum_j W*n_j = sum_j W  - 2*sum_j W*r_j,
// so lanes shuffle r directly, weights stored as -2W, and sum(W) folds into
// a per-column bias constant. The 1-2r FMA (output value) is off-chain.
//
// Unit->(lane,slot) assignment: greedy + local-search swap refinement to
// minimize max per-(column,slot) source count -> minimal shuffles/step.
// Warp-uniform template dispatch on the achieved cap. Exact SMEM overflow
// fallback (original weights, published n) for pathological draws.

#define BATCH  256
#define TLEN   4096
#define DIN    8
#define UNITS  64
#define CAPMAX 4
#define DEGCAP 12
#define CHUNK  64
#define NCHUNK (TLEN / CHUNK)
#define FULLMASK 0xffffffffu

__device__ int   g_unitOf[2][32];             // [slot][lane] -> unit id
__device__ int   g_lsrc[UNITS][2][CAPMAX];    // [col][slot][k] -> source lane
__device__ float g_lval[UNITS][2][CAPMAX];    // stored as -2*W
__device__ int   g_ncap;                      // max used slots (1..CAPMAX)
__device__ int   g_nover;
__device__ int   g_ovdst[256];
__device__ int   g_ovsrc[256];
__device__ float g_ovval[256];                // original W

__global__ void esn_prep_kernel(const float* __restrict__ W) {
    __shared__ int   s_cols[UNITS][DEGCAP];
    __shared__ int   s_deg[UNITS];
    __shared__ int   s_slot[UNITS], s_lane[UNITS];
    __shared__ int   s_ovn[UNITS];
    __shared__ int   s_cnt[UNITS][2];
    __shared__ int   s_ovsrc[UNITS][8];
    __shared__ float s_ovval[UNITS][8];

    const int tid = threadIdx.x;

    // Phase A: per-source-row nonzero column lists.
    if (tid < UNITS) {
        int d = 0;
        for (int c = 0; c < UNITS; ++c) {
            float v = W[tid * UNITS + c];
            if (v != 0.0f && d < DEGCAP) { s_cols[tid][d] = c; ++d; }
        }
        s_deg[tid] = d;
    }
    __syncthreads();

    // Phase B (serial, deterministic): greedy slot assignment + swap-based
    // local search minimizing max per-(column,slot) load, under the
    // constraint of exactly 32 units per slot.
    if (tid == 0) {
        int load[UNITS][2];
        for (int c = 0; c < UNITS; ++c) { load[c][0] = 0; load[c][1] = 0; }
        int cnt0 = 0, cnt1 = 0;
        for (int j = 0; j < UNITS; ++j) {
            int c0 = 0, c1 = 0;
            for (int k = 0; k < s_deg[j]; ++k) {
                int c = s_cols[j][k];
                if (load[c][0] > c0) c0 = load[c][0];
                if (load[c][1] > c1) c1 = load[c][1];
            }
            int s;
            if (cnt0 >= 32) s = 1;
            else if (cnt1 >= 32) s = 0;
            else if (c0 != c1) s = (c0 < c1) ? 0 : 1;
            else s = (cnt0 <= cnt1) ? 0 : 1;
            s_slot[j] = s;
            s_lane[j] = (s == 0) ? cnt0++ : cnt1++;
            for (int k = 0; k < s_deg[j]; ++k) load[s_cols[j][k]][s]++;
        }

        // Local search: swap (a in slot0, b in slot1) if it lowers the
        // global max load. Full recompute per trial (cheap at this size).
        for (int pass = 0; pass < 8; ++pass) {
            int curmax = 0;
            for (int c = 0; c < UNITS; ++c) {
                if (load[c][0] > curmax) curmax = load[c][0];
                if (load[c][1] > curmax) curmax = load[c][1];
            }
            if (curmax <= 1) break;
            bool improved = false;
            for (int a = 0; a < UNITS; ++a) {
                if (s_slot[a] != 0) continue;
                for (int b = 0; b < UNITS; ++b) {
                    if (s_slot[b] != 1) continue;
                    // trial swap
                    for (int k = 0; k < s_deg[a]; ++k) { load[s_cols[a][k]][0]--; load[s_cols[a][k]][1]++; }
                    for (int k = 0; k < s_deg[b]; ++k) { load[s_cols[b][k]][1]--; load[s_cols[b][k]][0]++; }
                    int nm = 0;
                    for (int c = 0; c < UNITS; ++c) {
                        if (load[c][0] > nm) nm = load[c][0];
                        if (load[c][1] > nm) nm = load[c][1];
                    }
                    if (nm < curmax) {
                        // accept (swap lane ids too, preserving 32/32)
                        int tl = s_lane[a]; s_lane[a] = s_lane[b]; s_lane[b] = tl;
                        s_slot[a] = 1; s_slot[b] = 0;
                        curmax = nm;
                        improved = true;
                        break;  // restart scan for unit a' (a now slot1)
                    } else {
                        // revert
                        for (int k = 0; k < s_deg[a]; ++k) { load[s_cols[a][k]][0]++; load[s_cols[a][k]][1]--; }
                        for (int k = 0; k < s_deg[b]; ++k) { load[s_cols[b][k]][1]++; load[s_cols[b][k]][0]--; }
                    }
                }
            }
            if (!improved) break;
        }
    }
    __syncthreads();

    // Phase C: per-column shuffle lists (weights -2W) + overflow + counts.
    if (tid < UNITS) {
        const int c = tid;
        int n0 = 0, n1 = 0, ovn = 0;
        for (int j = 0; j < UNITS; ++j) {
            float v = W[j * UNITS + c];
            if (v == 0.0f) continue;
            int s = s_slot[j];
            if (s == 0 && n0 < CAPMAX)      { g_lsrc[c][0][n0] = s_lane[j]; g_lval[c][0][n0] = -2.0f * v; ++n0; }
            else if (s == 1 && n1 < CAPMAX) { g_lsrc[c][1][n1] = s_lane[j]; g_lval[c][1][n1] = -2.0f * v; ++n1; }
            else if (ovn < 8)               { s_ovsrc[c][ovn] = j; s_ovval[c][ovn] = v; ++ovn; }
        }
        for (int k = n0; k < CAPMAX; ++k) { g_lsrc[c][0][k] = 0; g_lval[c][0][k] = 0.0f; }
        for (int k = n1; k < CAPMAX; ++k) { g_lsrc[c][1][k] = 0; g_lval[c][1][k] = 0.0f; }
        s_cnt[c][0] = n0; s_cnt[c][1] = n1;
        s_ovn[c] = ovn;
        g_unitOf[s_slot[tid]][s_lane[tid]] = tid;
    }
    __syncthreads();

    // Phase D (serial): compact overflow + max cap.
    if (tid == 0) {
        int n = 0, mx = 1;
        for (int c = 0; c < UNITS; ++c) {
            if (s_cnt[c][0] > mx) mx = s_cnt[c][0];
            if (s_cnt[c][1] > mx) mx = s_cnt[c][1];
            for (int k = 0; k < s_ovn[c]; ++k) {
                g_ovdst[n] = c; g_ovsrc[n] = s_ovsrc[c][k]; g_ovval[n] = s_ovval[c][k]; ++n;
            }
        }
        g_nover = n;
        g_ncap  = mx;
    }
}

__device__ __forceinline__ void cp_async16(void* smem_dst, const void* gmem_src) {
    uint32_t s = (uint32_t)__cvta_generic_to_shared(smem_dst);
    asm volatile("cp.async.cg.shared.global [%0], [%1], 16;\n" :: "r"(s), "l"(gmem_src));
}
__device__ __forceinline__ void cp_async_commit() {
    asm volatile("cp.async.commit_group;\n");
}
__device__ __forceinline__ void cp_async_wait1() {
    asm volatile("cp.async.wait_group 1;\n");
}

template <int NC>
__device__ __forceinline__ void time_loop(
    const int lane, const int u0, const int u1,
    const float (&win0)[DIN], const float (&win1)[DIN],
    const float bias0, const float bias1,
    const float* __restrict__ inp_b, float* __restrict__ out_b,
    float (&xin)[2][CHUNK * DIN], float (&sh)[UNITS],
    const int nover)
{
    // Shuffle lists (registers, length NC), weights already -2W.
    int   s00[NC], s01[NC], s10[NC], s11[NC];
    float v00[NC], v01[NC], v10[NC], v11[NC];
    float sw0 = 0.0f, sw1 = 0.0f;  // sum of -2W per column
#pragma unroll
    for (int k = 0; k < NC; ++k) {
        s00[k] = g_lsrc[u0][0][k];  v00[k] = g_lval[u0][0][k];
        s01[k] = g_lsrc[u0][1][k];  v01[k] = g_lval[u0][1][k];
        s10[k] = g_lsrc[u1][0][k];  v10[k] = g_lval[u1][0][k];
        s11[k] = g_lsrc[u1][1][k];  v11[k] = g_lval[u1][1][k];
        sw0 += v00[k] + v01[k];
        sw1 += v10[k] + v11[k];
    }
    // Folded bias: bias + sum(W_list) = bias - 0.5 * sum(-2W_list)
    const float B0 = bias0 - 0.5f * sw0;
    const float B1 = bias1 - 0.5f * sw1;

    float r0 = 0.5f, r1 = 0.5f;    // r = rcp(e+1); state n=0 -> r=0.5
    float n0s = 0.0f, n1s = 0.0f;  // output states (previous step)

    // Prefetch input chunks 0 and 1 (2048B each; lane copies 4x16B).
#pragma unroll
    for (int c = 0; c < 2; ++c) {
        const float* src = inp_b + c * CHUNK * DIN;
#pragma unroll
        for (int i = 0; i < 4; ++i) {
            int fo = lane * 16 + i * 4;
            cp_async16(&xin[c][fo], src + fo);
        }
        cp_async_commit();
    }

    float* optr0 = out_b + u0;
    float* optr1 = out_b + u1;

    for (int c = 0; c < NCHUNK; ++c) {
        cp_async_wait1();
        __syncwarp();
        const int buf = c & 1;

#pragma unroll 4
        for (int tt = 0; tt < CHUNK; ++tt) {
            const float4 xa = *(const float4*)&xin[buf][tt * DIN];
            const float4 xb = *(const float4*)&xin[buf][tt * DIN + 4];

            // Input projection (off-chain), 2-acc trees, folded bias.
            float q0 = fmaf(win0[0], xa.x, B0), q1 = win0[1] * xa.y;
            q0 = fmaf(win0[2], xa.z, q0); q1 = fmaf(win0[3], xa.w, q1);
            q0 = fmaf(win0[4], xb.x, q0); q1 = fmaf(win0[5], xb.y, q1);
            q0 = fmaf(win0[6], xb.z, q0); q1 = fmaf(win0[7], xb.w, q1);
            const float xp0 = q0 + q1;

            float p0 = fmaf(win1[0], xa.x, B1), p1 = win1[1] * xa.y;
            p0 = fmaf(win1[2], xa.z, p0); p1 = fmaf(win1[3], xa.w, p1);
            p0 = fmaf(win1[4], xb.x, p0); p1 = fmaf(win1[5], xb.y, p1);
            p0 = fmaf(win1[6], xb.z, p0); p1 = fmaf(win1[7], xb.w, p1);
            const float xp1 = p0 + p1;

            // Overflow publish (warp-uniform; normally skipped).
            if (nover) {
                sh[u0] = n0s; sh[u1] = n1s;
                __syncwarp();
            }

            // Recurrent gather on r (the critical chain).
            float a0 = xp0, a0b = 0.0f;
            float a1 = xp1, a1b = 0.0f;
#pragma unroll
            for (int k = 0; k < NC; ++k) {
                a0  = fmaf(v00[k], __shfl_sync(FULLMASK, r0, s00[k]), a0);
                a0b = fmaf(v01[k], __shfl_sync(FULLMASK, r1, s01[k]), a0b);
                a1  = fmaf(v10[k], __shfl_sync(FULLMASK, r0, s10[k]), a1);
                a1b = fmaf(v11[k], __shfl_sync(FULLMASK, r1, s11[k]), a1b);
            }
            float z0 = a0 + a0b;
            float z1 = a1 + a1b;

            if (nover) {
                for (int k = 0; k < nover; ++k) {
                    const float ctr = g_ovval[k] * sh[g_ovsrc[k]];
                    const int dd = g_ovdst[k];
                    if (dd == u0) z0 += ctr;
                    if (dd == u1) z1 += ctr;
                }
                __syncwarp();
            }

            // r = rcp(exp(2z)+1); chain mul+ex2+add+rcp = ~40 cyc.
            float e0, e1;
            asm("ex2.approx.f32 %0, %1;" : "=f"(e0) : "f"(z0 * 2.8853900817779268f));
            asm("ex2.approx.f32 %0, %1;" : "=f"(e1) : "f"(z1 * 2.8853900817779268f));
            asm("rcp.approx.f32 %0, %1;" : "=f"(r0) : "f"(e0 + 1.0f));
            asm("rcp.approx.f32 %0, %1;" : "=f"(r1) : "f"(e1 + 1.0f));

            // Output value n = 1 - 2r (off the critical chain).
            n0s = fmaf(-2.0f, r0, 1.0f);
            n1s = fmaf(-2.0f, r1, 1.0f);
            *optr0 = n0s;  optr0 += UNITS;
            *optr1 = n1s;  optr1 += UNITS;
        }

        // Prefetch chunk c+2 into the buffer just consumed.
        if (c + 2 < NCHUNK) {
            const float* src = inp_b + (c + 2) * CHUNK * DIN;
#pragma unroll
            for (int i = 0; i < 4; ++i) {
                int fo = lane * 16 + i * 4;
                cp_async16(&xin[buf][fo], src + fo);
            }
        }
        cp_async_commit();
    }
}

__global__ void __launch_bounds__(32)
esn_main_kernel(const float* __restrict__ inputs,
                const float* __restrict__ W_in,
                const float* __restrict__ bias,
                float* __restrict__ out) {
    const int lane = threadIdx.x;
    const int b    = blockIdx.x;

    __shared__ float xin[2][CHUNK * DIN];
    __shared__ float sh[UNITS];

    const int u0 = g_unitOf[0][lane];
    const int u1 = g_unitOf[1][lane];

    float win0[DIN], win1[DIN];
#pragma unroll
    for (int d = 0; d < DIN; ++d) {
        win0[d] = W_in[d * UNITS + u0];
        win1[d] = W_in[d * UNITS + u1];
    }
    const float b0 = bias[u0];
    const float b1 = bias[u1];

    const float* inp_b = inputs + (size_t)b * TLEN * DIN;
    float*       out_b = out    + (size_t)b * TLEN * UNITS;

    const int nover = g_nover;
    const int ncap  = g_ncap;      // warp-uniform dispatch

    if (ncap <= 1)
        time_loop<1>(lane, u0, u1, win0, win1, b0, b1, inp_b, out_b, xin, sh, nover);
    else if (ncap == 2)
        time_loop<2>(lane, u0, u1, win0, win1, b0, b1, inp_b, out_b, xin, sh, nover);
    else if (ncap == 3)
        time_loop<3>(lane, u0, u1, win0, win1, b0, b1, inp_b, out_b, xin, sh, nover);
    else
        time_loop<4>(lane, u0, u1, win0, win1, b0, b1, inp_b, out_b, xin, sh, nover);
}

extern "C" void kernel_launch(void* const* d_in, const int* in_sizes, int n_in,
                              void* d_out, int out_size) {
    const float* inputs = (const float*)d_in[0];   // [256, 4096, 8]
    const float* W_in   = (const float*)d_in[1];   // [8, 64]
    const float* bias   = (const float*)d_in[2];   // [64]
    const float* W_rec  = (const float*)d_in[3];   // [64, 64]
    float* out = (float*)d_out;                    // [256, 4096, 64]

    esn_prep_kernel<<<1, UNITS>>>(W_rec);
    esn_main_kernel<<<BATCH, 32>>>(inputs, W_in, bias, out);
}

// round 8
// speedup vs baseline: 1.0971x; 1.0971x over previous
#include <cuda_runtime.h>
#include <cuda_bf16.h>
#include <cstdint>

// ESN reservoir: B=256, T=4096, D=8, U=64, leaky=1.0
// state_t = tanh(x_proj_t + state_{t-1} @ W_rec), W_rec ~64 nnz total.
//
// State carried as r = rcp(exp(2z)+1)  (n = tanh(z) = 1 - 2r); weights -2W,
// sum(W) folded into per-column bias. Gather uses a per-lane ROUND schedule:
// round k = one shfl of r0 + one shfl of r1 per lane, each multiplied into
// both of the lane's accumulators with dual weights (one of them zero).
// Rounds R = max per-(lane, source-slot) product count (expected 2).
// Prep: degree-sorted antipodal pairing + orientation sweep (incremental,
// bounded). Exact SMEM overflow fallback for anything that doesn't fit.

#define BATCH  256
#define TLEN   4096
#define DIN    8
#define UNITS  64
#define RMAX   4
#define CHUNK  64
#define NCHUNK (TLEN / CHUNK)
#define FULLMASK 0xffffffffu

__device__ int   g_unitOf[2][32];           // [slot][lane] -> unit id
__device__ int   g_src[2][32][RMAX];        // [type A/B][lane][k] -> src lane
__device__ float g_wgt[2][2][32][RMAX];     // [type][zslot][lane][k] = -2W or 0
__device__ float g_fold[UNITS];             // sum of in-list W per column
__device__ int   g_R;                       // rounds (1..RMAX)
__device__ int   g_nover;
__device__ int   g_ovdst[160];
__device__ int   g_ovsrc[160];
__device__ float g_ovval[160];              // original W

__global__ void esn_prep_kernel(const float* __restrict__ W) {
    __shared__ int   s_csrc[UNITS][8];
    __shared__ float s_cval[UNITS][8];
    __shared__ int   s_cdeg[UNITS];
    __shared__ int   s_ovn[UNITS];
    __shared__ int   s_ovs[UNITS][4];
    __shared__ float s_ovv[UNITS][4];
    __shared__ int   s_laneOf[UNITS];

    const int tid = threadIdx.x;

    // Phase A (parallel): per-column source lists (cap 8, extras staged).
    if (tid < UNITS) {
        const int c = tid;
        int d = 0, ov = 0;
        for (int j = 0; j < UNITS; ++j) {
            float v = W[j * UNITS + c];
            if (v != 0.0f) {
                if (d < 8)       { s_csrc[c][d] = j; s_cval[c][d] = v; ++d; }
                else if (ov < 4) { s_ovs[c][ov] = j; s_ovv[c][ov] = v; ++ov; }
            }
        }
        s_cdeg[c] = d;
        s_ovn[c]  = ov;
    }
    // Zero emission arrays (parallel).
    if (tid < 32) {
        for (int t = 0; t < 2; ++t)
            for (int k = 0; k < RMAX; ++k) {
                g_src[t][tid][k] = 0;
                g_wgt[t][0][tid][k] = 0.0f;
                g_wgt[t][1][tid][k] = 0.0f;
            }
    }
    __syncthreads();

    // Phase B (serial, deterministic, bounded): pairing + orientation.
    if (tid == 0) {
        // Sort columns by in-degree desc (selection sort).
        int ord[UNITS];
        for (int i = 0; i < UNITS; ++i) ord[i] = i;
        for (int i = 0; i < UNITS - 1; ++i) {
            int best = i;
            for (int j = i + 1; j < UNITS; ++j)
                if (s_cdeg[ord[j]] > s_cdeg[ord[best]]) best = j;
            int t = ord[i]; ord[i] = ord[best]; ord[best] = t;
        }
        // Antipodal pairing: lane i owns (ord[i], ord[63-i]).
        int unitA[32], unitB[32], o[32];
        for (int i = 0; i < 32; ++i) {
            unitA[i] = ord[i];
            unitB[i] = ord[63 - i];
            o[i] = 0;
            s_laneOf[unitA[i]] = i;
            s_laneOf[unitB[i]] = i;
        }
        // Per-source destination lists (cap 8; beyond -> counted via col lists anyway).
        int rdeg[UNITS], rdst[UNITS][8];
        for (int j = 0; j < UNITS; ++j) rdeg[j] = 0;
        for (int c = 0; c < UNITS; ++c)
            for (int k = 0; k < s_cdeg[c]; ++k) {
                int j = s_csrc[c][k];
                if (rdeg[j] < 8) rdst[j][rdeg[j]++] = c;
            }
        // cnt[L][t] = # products into lane L's columns from slot-t sources.
        int cnt[32][2];
        for (int L = 0; L < 32; ++L) { cnt[L][0] = 0; cnt[L][1] = 0; }
        for (int c = 0; c < UNITS; ++c) {
            int L = s_laneOf[c];
            for (int k = 0; k < s_cdeg[c]; ++k) {
                int j = s_csrc[c][k];
                int p = s_laneOf[j];
                int t = (unitA[p] == j) ? o[p] : 1 - o[p];
                cnt[L][t]++;
            }
        }
        // Orientation sweeps (incremental apply/revert; objective = sum cnt^2).
        for (int pass = 0; pass < 6; ++pass) {
            bool improved = false;
            for (int p = 0; p < 32; ++p) {
                long before = 0;
                for (int L = 0; L < 32; ++L)
                    before += (long)cnt[L][0] * cnt[L][0] + (long)cnt[L][1] * cnt[L][1];
                const int tA = o[p];  // current slot of unitA[p]
                // apply flip: A's products tA -> 1-tA ; B's products 1-tA -> tA
                for (int k = 0; k < rdeg[unitA[p]]; ++k) {
                    int L = s_laneOf[rdst[unitA[p]][k]];
                    cnt[L][tA]--; cnt[L][1 - tA]++;
                }
                for (int k = 0; k < rdeg[unitB[p]]; ++k) {
                    int L = s_laneOf[rdst[unitB[p]][k]];
                    cnt[L][1 - tA]--; cnt[L][tA]++;
                }
                long after = 0;
                for (int L = 0; L < 32; ++L)
                    after += (long)cnt[L][0] * cnt[L][0] + (long)cnt[L][1] * cnt[L][1];
                if (after < before) {
                    o[p] ^= 1;
                    improved = true;
                } else {
                    // revert
                    for (int k = 0; k < rdeg[unitA[p]]; ++k) {
                        int L = s_laneOf[rdst[unitA[p]][k]];
                        cnt[L][1 - tA]--; cnt[L][tA]++;
                    }
                    for (int k = 0; k < rdeg[unitB[p]]; ++k) {
                        int L = s_laneOf[rdst[unitB[p]][k]];
                        cnt[L][tA]--; cnt[L][1 - tA]++;
                    }
                }
            }
            if (!improved) break;
        }

        // Emission.
        float fold[UNITS];
        for (int c = 0; c < UNITS; ++c) fold[c] = 0.0f;
        int fill[32][2];
        for (int L = 0; L < 32; ++L) { fill[L][0] = 0; fill[L][1] = 0; }
        int nov = 0;
        for (int c = 0; c < UNITS; ++c) {
            const int L  = s_laneOf[c];
            const int zs = (unitA[L] == c) ? o[L] : 1 - o[L];   // z-slot of column c
            for (int k = 0; k < s_cdeg[c]; ++k) {
                int   j = s_csrc[c][k];
                float v = s_cval[c][k];
                int   p = s_laneOf[j];
                int   t = (unitA[p] == j) ? o[p] : 1 - o[p];
                int   f = fill[L][t];
                if (f < RMAX) {
                    g_src[t][L][f]      = s_laneOf[j];
                    g_wgt[t][zs][L][f]  = -2.0f * v;
                    fold[c] += v;
                    fill[L][t] = f + 1;
                } else if (nov < 160) {
                    g_ovdst[nov] = c; g_ovsrc[nov] = j; g_ovval[nov] = v; ++nov;
                }
            }
            for (int k = 0; k < s_ovn[c] && nov < 160; ++k) {
                g_ovdst[nov] = c; g_ovsrc[nov] = s_ovs[c][k]; g_ovval[nov] = s_ovv[c][k]; ++nov;
            }
        }
        int R = 1;
        for (int L = 0; L < 32; ++L) {
            if (fill[L][0] > R) R = fill[L][0];
            if (fill[L][1] > R) R = fill[L][1];
        }
        g_R = R;
        g_nover = nov;
        for (int c = 0; c < UNITS; ++c) g_fold[c] = fold[c];
        for (int L = 0; L < 32; ++L) {
            g_unitOf[0][L] = o[L] ? unitB[L] : unitA[L];
            g_unitOf[1][L] = o[L] ? unitA[L] : unitB[L];
        }
    }
}

__device__ __forceinline__ void cp_async16(void* smem_dst, const void* gmem_src) {
    uint32_t s = (uint32_t)__cvta_generic_to_shared(smem_dst);
    asm volatile("cp.async.cg.shared.global [%0], [%1], 16;\n" :: "r"(s), "l"(gmem_src));
}
__device__ __forceinline__ void cp_async_commit() {
    asm volatile("cp.async.commit_group;\n");
}
__device__ __forceinline__ void cp_async_wait1() {
    asm volatile("cp.async.wait_group 1;\n");
}

template <int R>
__device__ __forceinline__ void time_loop(
    const int lane, const int u0, const int u1,
    const float (&win0)[DIN], const float (&win1)[DIN],
    const float B0, const float B1,
    const float* __restrict__ inp_b, float* __restrict__ out_b,
    float (&xin)[2][CHUNK * DIN], float (&sh)[UNITS],
    const int nover)
{
    // Round schedule (registers).
    int   sA[R], sB[R];
    float wA0[R], wA1[R], wB0[R], wB1[R];
#pragma unroll
    for (int k = 0; k < R; ++k) {
        sA[k]  = g_src[0][lane][k];
        sB[k]  = g_src[1][lane][k];
        wA0[k] = g_wgt[0][0][lane][k];
        wA1[k] = g_wgt[0][1][lane][k];
        wB0[k] = g_wgt[1][0][lane][k];
        wB1[k] = g_wgt[1][1][lane][k];
    }

    float r0 = 0.5f, r1 = 0.5f;    // r = rcp(e+1); state n=0 -> r=0.5
    float n0s = 0.0f, n1s = 0.0f;  // output values of previous step

    // Prefetch input chunks 0 and 1 (2048B each; lane copies 4x16B).
#pragma unroll
    for (int c = 0; c < 2; ++c) {
        const float* src = inp_b + c * CHUNK * DIN;
#pragma unroll
        for (int i = 0; i < 4; ++i) {
            int fo = lane * 16 + i * 4;
            cp_async16(&xin[c][fo], src + fo);
        }
        cp_async_commit();
    }

    float* optr0 = out_b + u0;
    float* optr1 = out_b + u1;

    for (int c = 0; c < NCHUNK; ++c) {
        cp_async_wait1();
        __syncwarp();
        const int buf = c & 1;

#pragma unroll 4
        for (int tt = 0; tt < CHUNK; ++tt) {
            const float4 xa = *(const float4*)&xin[buf][tt * DIN];
            const float4 xb = *(const float4*)&xin[buf][tt * DIN + 4];

            // Input projection (off-chain), 2-acc trees, folded bias.
            float q0 = fmaf(win0[0], xa.x, B0), q1 = win0[1] * xa.y;
            q0 = fmaf(win0[2], xa.z, q0); q1 = fmaf(win0[3], xa.w, q1);
            q0 = fmaf(win0[4], xb.x, q0); q1 = fmaf(win0[5], xb.y, q1);
            q0 = fmaf(win0[6], xb.z, q0); q1 = fmaf(win0[7], xb.w, q1);
            const float xp0 = q0 + q1;

            float p0 = fmaf(win1[0], xa.x, B1), p1 = win1[1] * xa.y;
            p0 = fmaf(win1[2], xa.z, p0); p1 = fmaf(win1[3], xa.w, p1);
            p0 = fmaf(win1[4], xb.x, p0); p1 = fmaf(win1[5], xb.y, p1);
            p0 = fmaf(win1[6], xb.z, p0); p1 = fmaf(win1[7], xb.w, p1);
            const float xp1 = p0 + p1;

            // Overflow publish (warp-uniform; normally skipped).
            if (nover) {
                sh[u0] = n0s; sh[u1] = n1s;
                __syncwarp();
            }

            // Round gather: 2 shuffles + 4 FMAs per round.
            float z0a = xp0, z1a = xp1, z0b = 0.0f, z1b = 0.0f;
#pragma unroll
            for (int k = 0; k < R; ++k) {
                const float va = __shfl_sync(FULLMASK, r0, sA[k]);
                z0a = fmaf(wA0[k], va, z0a);
                z1a = fmaf(wA1[k], va, z1a);
                const float vb = __shfl_sync(FULLMASK, r1, sB[k]);
                z0b = fmaf(wB0[k], vb, z0b);
                z1b = fmaf(wB1[k], vb, z1b);
            }
            float z0 = z0a + z0b;
            float z1 = z1a + z1b;

            if (nover) {
                for (int k = 0; k < nover; ++k) {
                    const float ctr = g_ovval[k] * sh[g_ovsrc[k]];
                    const int dd = g_ovdst[k];
                    if (dd == u0) z0 += ctr;
                    if (dd == u1) z1 += ctr;
                }
                __syncwarp();
            }

            // r = rcp(exp(2z)+1)
            float e0, e1;
            asm("ex2.approx.f32 %0, %1;" : "=f"(e0) : "f"(z0 * 2.8853900817779268f));
            asm("ex2.approx.f32 %0, %1;" : "=f"(e1) : "f"(z1 * 2.8853900817779268f));
            asm("rcp.approx.f32 %0, %1;" : "=f"(r0) : "f"(e0 + 1.0f));
            asm("rcp.approx.f32 %0, %1;" : "=f"(r1) : "f"(e1 + 1.0f));

            // Output n = 1 - 2r (off the critical chain).
            n0s = fmaf(-2.0f, r0, 1.0f);
            n1s = fmaf(-2.0f, r1, 1.0f);
            *optr0 = n0s;  optr0 += UNITS;
            *optr1 = n1s;  optr1 += UNITS;
        }

        // Prefetch chunk c+2 into the buffer just consumed.
        if (c + 2 < NCHUNK) {
            const float* src = inp_b + (c + 2) * CHUNK * DIN;
#pragma unroll
            for (int i = 0; i < 4; ++i) {
                int fo = lane * 16 + i * 4;
                cp_async16(&xin[buf][fo], src + fo);
            }
        }
        cp_async_commit();
    }
}

__global__ void __launch_bounds__(32)
esn_main_kernel(const float* __restrict__ inputs,
                const float* __restrict__ W_in,
                const float* __restrict__ bias,
                float* __restrict__ out) {
    const int lane = threadIdx.x;
    const int b    = blockIdx.x;

    __shared__ float xin[2][CHUNK * DIN];
    __shared__ float sh[UNITS];

    const int u0 = g_unitOf[0][lane];
    const int u1 = g_unitOf[1][lane];

    float win0[DIN], win1[DIN];
#pragma unroll
    for (int d = 0; d < DIN; ++d) {
        win0[d] = W_in[d * UNITS + u0];
        win1[d] = W_in[d * UNITS + u1];
    }
    // Folded bias: bias + sum(W_inlist).
    const float B0 = bias[u0] + g_fold[u0];
    const float B1 = bias[u1] + g_fold[u1];

    const float* inp_b = inputs + (size_t)b * TLEN * DIN;
    float*       out_b = out    + (size_t)b * TLEN * UNITS;

    const int nover = g_nover;
    const int R     = g_R;        // warp-uniform dispatch

    if (R <= 1)
        time_loop<1>(lane, u0, u1, win0, win1, B0, B1, inp_b, out_b, xin, sh, nover);
    else if (R == 2)
        time_loop<2>(lane, u0, u1, win0, win1, B0, B1, inp_b, out_b, xin, sh, nover);
    else if (R == 3)
        time_loop<3>(lane, u0, u1, win0, win1, B0, B1, inp_b, out_b, xin, sh, nover);
    else
        time_loop<4>(lane, u0, u1, win0, win1, B0, B1, inp_b, out_b, xin, sh, nover);
}

extern "C" void kernel_launch(void* const* d_in, const int* in_sizes, int n_in,
                              void* d_out, int out_size) {
    const float* inputs = (const float*)d_in[0];   // [256, 4096, 8]
    const float* W_in   = (const float*)d_in[1];   // [8, 64]
    const float* bias   = (const float*)d_in[2];   // [64]
    const float* W_rec  = (const float*)d_in[3];   // [64, 64]
    float* out = (float*)d_out;                    // [256, 4096, 64]

    esn_prep_kernel<<<1, UNITS>>>(W_rec);
    esn_main_kernel<<<BATCH, 32>>>(inputs, W_in, bias, out);
}

// round 9
// speedup vs baseline: 2.0575x; 1.8754x over previous
#include <cuda_runtime.h>
#include <cuda_bf16.h>
#include <cstdint>

// ESN reservoir: B=256, T=4096, D=8, U=64, leaky=1.0
// state_t = tanh(x_proj_t + state_{t-1} @ W_rec), W_rec ~64 nnz total.
//
// State carried as r = rcp(exp(2z)+1)  (n = tanh(z) = 1 - 2r); weights -2W,
// sum(W) folded into per-column bias. Per-(column,slot) shuffle lists from a
// fast greedy slot balancer; warp-uniform template dispatch on achieved cap.
// KEY: 2 warps per block (one batch each) so co-resident warps land on
// DIFFERENT SMSPs (SMSP = intra-block wid % 4); 128 blocks -> 1 block/SM ->
// one warp per SMSP, no scheduler contention.

#define BATCH  256
#define TLEN   4096
#define DIN    8
#define UNITS  64
#define CAPMAX 4
#define DEGCAP 12
#define CHUNK  64
#define NCHUNK (TLEN / CHUNK)
#define FULLMASK 0xffffffffu

__device__ int   g_unitOf[2][32];             // [slot][lane] -> unit id
__device__ int   g_lsrc[UNITS][2][CAPMAX];    // [col][slot][k] -> source lane
__device__ float g_lval[UNITS][2][CAPMAX];    // stored as -2*W
__device__ int   g_ncap;                      // max used slots (1..CAPMAX)
__device__ int   g_nover;
__device__ int   g_ovdst[256];
__device__ int   g_ovsrc[256];
__device__ float g_ovval[256];                // original W

__global__ void esn_prep_kernel(const float* __restrict__ W) {
    __shared__ int   s_cols[UNITS][DEGCAP];
    __shared__ int   s_deg[UNITS];
    __shared__ int   s_slot[UNITS], s_lane[UNITS];
    __shared__ int   s_ovn[UNITS];
    __shared__ int   s_cnt[UNITS][2];
    __shared__ int   s_ovsrc[UNITS][8];
    __shared__ float s_ovval[UNITS][8];

    const int tid = threadIdx.x;

    // Phase A: per-source-row nonzero column lists.
    if (tid < UNITS) {
        int d = 0;
        for (int c = 0; c < UNITS; ++c) {
            float v = W[tid * UNITS + c];
            if (v != 0.0f && d < DEGCAP) { s_cols[tid][d] = c; ++d; }
        }
        s_deg[tid] = d;
    }
    __syncthreads();

    // Phase B (serial, deterministic, FAST): greedy slot assignment
    // balancing each column's source count across the two register slots.
    if (tid == 0) {
        int load[UNITS][2];
        for (int c = 0; c < UNITS; ++c) { load[c][0] = 0; load[c][1] = 0; }
        int cnt0 = 0, cnt1 = 0;
        for (int j = 0; j < UNITS; ++j) {
            int c0 = 0, c1 = 0;
            for (int k = 0; k < s_deg[j]; ++k) {
                int c = s_cols[j][k];
                if (load[c][0] > c0) c0 = load[c][0];
                if (load[c][1] > c1) c1 = load[c][1];
            }
            int s;
            if (cnt0 >= 32) s = 1;
            else if (cnt1 >= 32) s = 0;
            else if (c0 != c1) s = (c0 < c1) ? 0 : 1;
            else s = (cnt0 <= cnt1) ? 0 : 1;
            s_slot[j] = s;
            s_lane[j] = (s == 0) ? cnt0++ : cnt1++;
            for (int k = 0; k < s_deg[j]; ++k) load[s_cols[j][k]][s]++;
        }
    }
    __syncthreads();

    // Phase C: per-column shuffle lists (weights -2W) + overflow + counts.
    if (tid < UNITS) {
        const int c = tid;
        int n0 = 0, n1 = 0, ovn = 0;
        for (int j = 0; j < UNITS; ++j) {
            float v = W[j * UNITS + c];
            if (v == 0.0f) continue;
            int s = s_slot[j];
            if (s == 0 && n0 < CAPMAX)      { g_lsrc[c][0][n0] = s_lane[j]; g_lval[c][0][n0] = -2.0f * v; ++n0; }
            else if (s == 1 && n1 < CAPMAX) { g_lsrc[c][1][n1] = s_lane[j]; g_lval[c][1][n1] = -2.0f * v; ++n1; }
            else if (ovn < 8)               { s_ovsrc[c][ovn] = j; s_ovval[c][ovn] = v; ++ovn; }
        }
        for (int k = n0; k < CAPMAX; ++k) { g_lsrc[c][0][k] = 0; g_lval[c][0][k] = 0.0f; }
        for (int k = n1; k < CAPMAX; ++k) { g_lsrc[c][1][k] = 0; g_lval[c][1][k] = 0.0f; }
        s_cnt[c][0] = n0; s_cnt[c][1] = n1;
        s_ovn[c] = ovn;
        g_unitOf[s_slot[tid]][s_lane[tid]] = tid;
    }
    __syncthreads();

    // Phase D (serial): compact overflow + max cap.
    if (tid == 0) {
        int n = 0, mx = 1;
        for (int c = 0; c < UNITS; ++c) {
            if (s_cnt[c][0] > mx) mx = s_cnt[c][0];
            if (s_cnt[c][1] > mx) mx = s_cnt[c][1];
            for (int k = 0; k < s_ovn[c]; ++k) {
                g_ovdst[n] = c; g_ovsrc[n] = s_ovsrc[c][k]; g_ovval[n] = s_ovval[c][k]; ++n;
            }
        }
        g_nover = n;
        g_ncap  = mx;
    }
}

__device__ __forceinline__ void cp_async16(void* smem_dst, const void* gmem_src) {
    uint32_t s = (uint32_t)__cvta_generic_to_shared(smem_dst);
    asm volatile("cp.async.cg.shared.global [%0], [%1], 16;\n" :: "r"(s), "l"(gmem_src));
}
__device__ __forceinline__ void cp_async_commit() {
    asm volatile("cp.async.commit_group;\n");
}
__device__ __forceinline__ void cp_async_wait1() {
    asm volatile("cp.async.wait_group 1;\n");
}

template <int NC>
__device__ __forceinline__ void time_loop(
    const int lane, const int u0, const int u1,
    const float (&win0)[DIN], const float (&win1)[DIN],
    const float bias0, const float bias1,
    const float* __restrict__ inp_b, float* __restrict__ out_b,
    float (&xin)[2][CHUNK * DIN], float (&sh)[UNITS],
    const int nover)
{
    // Shuffle lists (registers, length NC), weights already -2W.
    int   s00[NC], s01[NC], s10[NC], s11[NC];
    float v00[NC], v01[NC], v10[NC], v11[NC];
    float sw0 = 0.0f, sw1 = 0.0f;  // sum of -2W per column
#pragma unroll
    for (int k = 0; k < NC; ++k) {
        s00[k] = g_lsrc[u0][0][k];  v00[k] = g_lval[u0][0][k];
        s01[k] = g_lsrc[u0][1][k];  v01[k] = g_lval[u0][1][k];
        s10[k] = g_lsrc[u1][0][k];  v10[k] = g_lval[u1][0][k];
        s11[k] = g_lsrc[u1][1][k];  v11[k] = g_lval[u1][1][k];
        sw0 += v00[k] + v01[k];
        sw1 += v10[k] + v11[k];
    }
    // Folded bias: bias + sum(W_list) = bias - 0.5 * sum(-2W_list)
    const float B0 = bias0 - 0.5f * sw0;
    const float B1 = bias1 - 0.5f * sw1;

    float r0 = 0.5f, r1 = 0.5f;    // r = rcp(e+1); state n=0 -> r=0.5
    float n0s = 0.0f, n1s = 0.0f;  // output values of previous step

    // Prefetch input chunks 0 and 1 (2048B each; lane copies 4x16B).
#pragma unroll
    for (int c = 0; c < 2; ++c) {
        const float* src = inp_b + c * CHUNK * DIN;
#pragma unroll
        for (int i = 0; i < 4; ++i) {
            int fo = lane * 16 + i * 4;
            cp_async16(&xin[c][fo], src + fo);
        }
        cp_async_commit();
    }

    float* optr0 = out_b + u0;
    float* optr1 = out_b + u1;

    for (int c = 0; c < NCHUNK; ++c) {
        cp_async_wait1();
        __syncwarp();
        const int buf = c & 1;

#pragma unroll 4
        for (int tt = 0; tt < CHUNK; ++tt) {
            const float4 xa = *(const float4*)&xin[buf][tt * DIN];
            const float4 xb = *(const float4*)&xin[buf][tt * DIN + 4];

            // Input projection (off-chain), 2-acc trees, folded bias.
            float q0 = fmaf(win0[0], xa.x, B0), q1 = win0[1] * xa.y;
            q0 = fmaf(win0[2], xa.z, q0); q1 = fmaf(win0[3], xa.w, q1);
            q0 = fmaf(win0[4], xb.x, q0); q1 = fmaf(win0[5], xb.y, q1);
            q0 = fmaf(win0[6], xb.z, q0); q1 = fmaf(win0[7], xb.w, q1);
            const float xp0 = q0 + q1;

            float p0 = fmaf(win1[0], xa.x, B1), p1 = win1[1] * xa.y;
            p0 = fmaf(win1[2], xa.z, p0); p1 = fmaf(win1[3], xa.w, p1);
            p0 = fmaf(win1[4], xb.x, p0); p1 = fmaf(win1[5], xb.y, p1);
            p0 = fmaf(win1[6], xb.z, p0); p1 = fmaf(win1[7], xb.w, p1);
            const float xp1 = p0 + p1;

            // Overflow publish (warp-uniform; normally skipped).
            if (nover) {
                sh[u0] = n0s; sh[u1] = n1s;
                __syncwarp();
            }

            // Recurrent gather on r (the critical chain).
            float a0 = xp0, a0b = 0.0f;
            float a1 = xp1, a1b = 0.0f;
#pragma unroll
            for (int k = 0; k < NC; ++k) {
                a0  = fmaf(v00[k], __shfl_sync(FULLMASK, r0, s00[k]), a0);
                a0b = fmaf(v01[k], __shfl_sync(FULLMASK, r1, s01[k]), a0b);
                a1  = fmaf(v10[k], __shfl_sync(FULLMASK, r0, s10[k]), a1);
                a1b = fmaf(v11[k], __shfl_sync(FULLMASK, r1, s11[k]), a1b);
            }
            float z0 = a0 + a0b;
            float z1 = a1 + a1b;

            if (nover) {
                for (int k = 0; k < nover; ++k) {
                    const float ctr = g_ovval[k] * sh[g_ovsrc[k]];
                    const int dd = g_ovdst[k];
                    if (dd == u0) z0 += ctr;
                    if (dd == u1) z1 += ctr;
                }
                __syncwarp();
            }

            // r = rcp(exp(2z)+1); chain mul+ex2+add+rcp.
            float e0, e1;
            asm("ex2.approx.f32 %0, %1;" : "=f"(e0) : "f"(z0 * 2.8853900817779268f));
            asm("ex2.approx.f32 %0, %1;" : "=f"(e1) : "f"(z1 * 2.8853900817779268f));
            asm("rcp.approx.f32 %0, %1;" : "=f"(r0) : "f"(e0 + 1.0f));
            asm("rcp.approx.f32 %0, %1;" : "=f"(r1) : "f"(e1 + 1.0f));

            // Output value n = 1 - 2r (off the critical chain).
            n0s = fmaf(-2.0f, r0, 1.0f);
            n1s = fmaf(-2.0f, r1, 1.0f);
            *optr0 = n0s;  optr0 += UNITS;
            *optr1 = n1s;  optr1 += UNITS;
        }

        // Prefetch chunk c+2 into the buffer just consumed.
        if (c + 2 < NCHUNK) {
            const float* src = inp_b + (c + 2) * CHUNK * DIN;
#pragma unroll
            for (int i = 0; i < 4; ++i) {
                int fo = lane * 16 + i * 4;
                cp_async16(&xin[buf][fo], src + fo);
            }
        }
        cp_async_commit();
    }
}

__global__ void __launch_bounds__(64)
esn_main_kernel(const float* __restrict__ inputs,
                const float* __restrict__ W_in,
                const float* __restrict__ bias,
                float* __restrict__ out) {
    const int lane = threadIdx.x & 31;
    const int warp = threadIdx.x >> 5;            // 0..1 -> SMSP 0..1
    const int b    = blockIdx.x * 2 + warp;       // one batch per warp

    __shared__ float xin[2][2][CHUNK * DIN];      // [warp][buf][..]
    __shared__ float sh[2][UNITS];                // [warp][..]

    const int u0 = g_unitOf[0][lane];
    const int u1 = g_unitOf[1][lane];

    float win0[DIN], win1[DIN];
#pragma unroll
    for (int d = 0; d < DIN; ++d) {
        win0[d] = W_in[d * UNITS + u0];
        win1[d] = W_in[d * UNITS + u1];
    }
    const float b0 = bias[u0];
    const float b1 = bias[u1];

    const float* inp_b = inputs + (size_t)b * TLEN * DIN;
    float*       out_b = out    + (size_t)b * TLEN * UNITS;

    const int nover = g_nover;
    const int ncap  = g_ncap;      // warp-uniform dispatch

    if (ncap <= 1)
        time_loop<1>(lane, u0, u1, win0, win1, b0, b1, inp_b, out_b, xin[warp], sh[warp], nover);
    else if (ncap == 2)
        time_loop<2>(lane, u0, u1, win0, win1, b0, b1, inp_b, out_b, xin[warp], sh[warp], nover);
    else if (ncap == 3)
        time_loop<3>(lane, u0, u1, win0, win1, b0, b1, inp_b, out_b, xin[warp], sh[warp], nover);
    else
        time_loop<4>(lane, u0, u1, win0, win1, b0, b1, inp_b, out_b, xin[warp], sh[warp], nover);
}

extern "C" void kernel_launch(void* const* d_in, const int* in_sizes, int n_in,
                              void* d_out, int out_size) {
    const float* inputs = (const float*)d_in[0];   // [256, 4096, 8]
    const float* W_in   = (const float*)d_in[1];   // [8, 64]
    const float* bias   = (const float*)d_in[2];   // [64]
    const float* W_rec  = (const float*)d_in[3];   // [64, 64]
    float* out = (float*)d_out;                    // [256, 4096, 64]

    esn_prep_kernel<<<1, UNITS>>>(W_rec);
    esn_main_kernel<<<BATCH / 2, 64>>>(inputs, W_in, bias, out);
}

// round 10
// speedup vs baseline: 2.2490x; 1.0931x over previous
#include <cuda_runtime.h>
#include <cuda_bf16.h>
#include <cstdint>

// ESN reservoir: B=256, T=4096, D=8, U=64, leaky=1.0
// state_t = tanh(x_proj_t + state_{t-1} @ W_rec), W_rec ~64 nnz total.
//
// State carried as r = rcp(exp2(zk)+1) where zk = (2/ln2)*z, n = 1-2r.
// All weights/biases pre-scaled by K=2/ln2 so no multiply precedes ex2.
// Recurrent weights stored as -2K*W; sum(K*W) folded into bias.
// Per-(column,slot) shuffle lists from greedy balancer + BOUNDED incremental
// swap repair (O(deg) per trial, no rescans) targeting cap<=2.
// Config: 256 blocks x 32 threads (measured best). Exact SMEM overflow
// fallback for pathological draws; warp-uniform template dispatch on cap.

#define BATCH  256
#define TLEN   4096
#define DIN    8
#define UNITS  64
#define CAPMAX 4
#define DEGCAP 12
#define CHUNK  64
#define NCHUNK (TLEN / CHUNK)
#define FULLMASK 0xffffffffu
#define KSC 2.8853900817779268f   // 2/ln2

__device__ int   g_unitOf[2][32];             // [slot][lane] -> unit id
__device__ int   g_lsrc[UNITS][2][CAPMAX];    // [col][slot][k] -> source lane
__device__ float g_lval[UNITS][2][CAPMAX];    // stored as -2*K*W
__device__ int   g_ncap;                      // max used slots (1..CAPMAX)
__device__ int   g_nover;
__device__ int   g_ovdst[256];
__device__ int   g_ovsrc[256];
__device__ float g_ovval[256];                // K*W

__global__ void esn_prep_kernel(const float* __restrict__ W) {
    __shared__ int   s_cols[UNITS][DEGCAP];
    __shared__ int   s_deg[UNITS];
    __shared__ int   s_slot[UNITS], s_lane[UNITS];
    __shared__ int   s_ovn[UNITS];
    __shared__ int   s_cnt[UNITS][2];
    __shared__ int   s_ovsrc[UNITS][8];
    __shared__ float s_ovval[UNITS][8];

    const int tid = threadIdx.x;

    // Phase A: per-source-row nonzero column lists.
    if (tid < UNITS) {
        int d = 0;
        for (int c = 0; c < UNITS; ++c) {
            float v = W[tid * UNITS + c];
            if (v != 0.0f && d < DEGCAP) { s_cols[tid][d] = c; ++d; }
        }
        s_deg[tid] = d;
    }
    __syncthreads();

    // Phase B (serial, deterministic): fast greedy + bounded repair.
    if (tid == 0) {
        int load[UNITS][2];
        for (int c = 0; c < UNITS; ++c) { load[c][0] = 0; load[c][1] = 0; }
        int cnt0 = 0, cnt1 = 0;
        for (int j = 0; j < UNITS; ++j) {
            int c0 = 0, c1 = 0;
            for (int k = 0; k < s_deg[j]; ++k) {
                int c = s_cols[j][k];
                if (load[c][0] > c0) c0 = load[c][0];
                if (load[c][1] > c1) c1 = load[c][1];
            }
            int s;
            if (cnt0 >= 32) s = 1;
            else if (cnt1 >= 32) s = 0;
            else if (c0 != c1) s = (c0 < c1) ? 0 : 1;
            else s = (cnt0 <= cnt1) ? 0 : 1;
            s_slot[j] = s;
            s_lane[j] = (s == 0) ? cnt0++ : cnt1++;
            for (int k = 0; k < s_deg[j]; ++k) load[s_cols[j][k]][s]++;
        }

        // Bounded repair: minimize T = sum over cells of max(load-2,0).
        // Trials only for units feeding an overloaded cell; O(deg) deltas.
        for (int pass = 0; pass < 3; ++pass) {
            bool any = false;
            for (int a = 0; a < UNITS; ++a) {
                const int sa = s_slot[a];
                bool hot = false;
                for (int k = 0; k < s_deg[a]; ++k)
                    if (load[s_cols[a][k]][sa] > 2) { hot = true; break; }
                if (!hot) continue;
                for (int b = 0; b < UNITS; ++b) {
                    if (s_slot[b] != 1 - sa) continue;
                    const int sb = 1 - sa;
                    // badness before, over affected columns (both slots)
                    int before = 0;
                    for (int k = 0; k < s_deg[a]; ++k) {
                        int c = s_cols[a][k];
                        before += (load[c][0] > 2 ? load[c][0] - 2 : 0)
                                + (load[c][1] > 2 ? load[c][1] - 2 : 0);
                    }
                    for (int k = 0; k < s_deg[b]; ++k) {
                        int c = s_cols[b][k];
                        before += (load[c][0] > 2 ? load[c][0] - 2 : 0)
                                + (load[c][1] > 2 ? load[c][1] - 2 : 0);
                    }
                    // apply swap
                    for (int k = 0; k < s_deg[a]; ++k) { int c = s_cols[a][k]; load[c][sa]--; load[c][sb]++; }
                    for (int k = 0; k < s_deg[b]; ++k) { int c = s_cols[b][k]; load[c][sb]--; load[c][sa]++; }
                    int after = 0;
                    for (int k = 0; k < s_deg[a]; ++k) {
                        int c = s_cols[a][k];
                        after += (load[c][0] > 2 ? load[c][0] - 2 : 0)
                               + (load[c][1] > 2 ? load[c][1] - 2 : 0);
                    }
                    for (int k = 0; k < s_deg[b]; ++k) {
                        int c = s_cols[b][k];
                        after += (load[c][0] > 2 ? load[c][0] - 2 : 0)
                               + (load[c][1] > 2 ? load[c][1] - 2 : 0);
                    }
                    // (overlap columns double-counted identically in both)
                    if (after < before) {
                        int tl = s_lane[a]; s_lane[a] = s_lane[b]; s_lane[b] = tl;
                        s_slot[a] = sb; s_slot[b] = sa;
                        any = true;
                        break;  // unit a moved; go to next a
                    } else {
                        // revert
                        for (int k = 0; k < s_deg[a]; ++k) { int c = s_cols[a][k]; load[c][sb]--; load[c][sa]++; }
                        for (int k = 0; k < s_deg[b]; ++k) { int c = s_cols[b][k]; load[c][sa]--; load[c][sb]++; }
                    }
                }
            }
            if (!any) break;
        }
    }
    __syncthreads();

    // Phase C: per-column shuffle lists (weights -2K*W) + overflow + counts.
    if (tid < UNITS) {
        const int c = tid;
        int n0 = 0, n1 = 0, ovn = 0;
        for (int j = 0; j < UNITS; ++j) {
            float v = W[j * UNITS + c];
            if (v == 0.0f) continue;
            int s = s_slot[j];
            if (s == 0 && n0 < CAPMAX)      { g_lsrc[c][0][n0] = s_lane[j]; g_lval[c][0][n0] = -2.0f * KSC * v; ++n0; }
            else if (s == 1 && n1 < CAPMAX) { g_lsrc[c][1][n1] = s_lane[j]; g_lval[c][1][n1] = -2.0f * KSC * v; ++n1; }
            else if (ovn < 8)               { s_ovsrc[c][ovn] = j; s_ovval[c][ovn] = KSC * v; ++ovn; }
        }
        for (int k = n0; k < CAPMAX; ++k) { g_lsrc[c][0][k] = 0; g_lval[c][0][k] = 0.0f; }
        for (int k = n1; k < CAPMAX; ++k) { g_lsrc[c][1][k] = 0; g_lval[c][1][k] = 0.0f; }
        s_cnt[c][0] = n0; s_cnt[c][1] = n1;
        s_ovn[c] = ovn;
        g_unitOf[s_slot[tid]][s_lane[tid]] = tid;
    }
    __syncthreads();

    // Phase D (serial): compact overflow + max cap.
    if (tid == 0) {
        int n = 0, mx = 1;
        for (int c = 0; c < UNITS; ++c) {
            if (s_cnt[c][0] > mx) mx = s_cnt[c][0];
            if (s_cnt[c][1] > mx) mx = s_cnt[c][1];
            for (int k = 0; k < s_ovn[c]; ++k) {
                g_ovdst[n] = c; g_ovsrc[n] = s_ovsrc[c][k]; g_ovval[n] = s_ovval[c][k]; ++n;
            }
        }
        g_nover = n;
        g_ncap  = mx;
    }
}

__device__ __forceinline__ void cp_async16(void* smem_dst, const void* gmem_src) {
    uint32_t s = (uint32_t)__cvta_generic_to_shared(smem_dst);
    asm volatile("cp.async.cg.shared.global [%0], [%1], 16;\n" :: "r"(s), "l"(gmem_src));
}
__device__ __forceinline__ void cp_async_commit() {
    asm volatile("cp.async.commit_group;\n");
}
__device__ __forceinline__ void cp_async_wait1() {
    asm volatile("cp.async.wait_group 1;\n");
}

template <int NC>
__device__ __forceinline__ void time_loop(
    const int lane, const int u0, const int u1,
    const float (&win0)[DIN], const float (&win1)[DIN],
    const float bias0, const float bias1,   // already K-scaled
    const float* __restrict__ inp_b, float* __restrict__ out_b,
    float (&xin)[2][CHUNK * DIN], float (&sh)[UNITS],
    const int nover)
{
    // Shuffle lists (registers, length NC), weights already -2K*W.
    int   s00[NC], s01[NC], s10[NC], s11[NC];
    float v00[NC], v01[NC], v10[NC], v11[NC];
    float sw0 = 0.0f, sw1 = 0.0f;  // sum of -2K*W per column
#pragma unroll
    for (int k = 0; k < NC; ++k) {
        s00[k] = g_lsrc[u0][0][k];  v00[k] = g_lval[u0][0][k];
        s01[k] = g_lsrc[u0][1][k];  v01[k] = g_lval[u0][1][k];
        s10[k] = g_lsrc[u1][0][k];  v10[k] = g_lval[u1][0][k];
        s11[k] = g_lsrc[u1][1][k];  v11[k] = g_lval[u1][1][k];
        sw0 += v00[k] + v01[k];
        sw1 += v10[k] + v11[k];
    }
    // Folded bias: K*bias + K*sum(W_list) = K*bias - 0.5*sum(-2K*W_list)
    const float B0 = bias0 - 0.5f * sw0;
    const float B1 = bias1 - 0.5f * sw1;

    float r0 = 0.5f, r1 = 0.5f;    // r = rcp(e+1); state n=0 -> r=0.5
    float n0s = 0.0f, n1s = 0.0f;  // output values of previous step

    // Prefetch input chunks 0 and 1 (2048B each; lane copies 4x16B).
#pragma unroll
    for (int c = 0; c < 2; ++c) {
        const float* src = inp_b + c * CHUNK * DIN;
#pragma unroll
        for (int i = 0; i < 4; ++i) {
            int fo = lane * 16 + i * 4;
            cp_async16(&xin[c][fo], src + fo);
        }
        cp_async_commit();
    }

    float* optr0 = out_b + u0;
    float* optr1 = out_b + u1;

    for (int c = 0; c < NCHUNK; ++c) {
        cp_async_wait1();
        __syncwarp();
        const int buf = c & 1;

#pragma unroll 4
        for (int tt = 0; tt < CHUNK; ++tt) {
            const float4 xa = *(const float4*)&xin[buf][tt * DIN];
            const float4 xb = *(const float4*)&xin[buf][tt * DIN + 4];

            // Input projection (off-chain), 2-acc trees, K-scaled weights.
            float q0 = fmaf(win0[0], xa.x, B0), q1 = win0[1] * xa.y;
            q0 = fmaf(win0[2], xa.z, q0); q1 = fmaf(win0[3], xa.w, q1);
            q0 = fmaf(win0[4], xb.x, q0); q1 = fmaf(win0[5], xb.y, q1);
            q0 = fmaf(win0[6], xb.z, q0); q1 = fmaf(win0[7], xb.w, q1);
            const float xp0 = q0 + q1;

            float p0 = fmaf(win1[0], xa.x, B1), p1 = win1[1] * xa.y;
            p0 = fmaf(win1[2], xa.z, p0); p1 = fmaf(win1[3], xa.w, p1);
            p0 = fmaf(win1[4], xb.x, p0); p1 = fmaf(win1[5], xb.y, p1);
            p0 = fmaf(win1[6], xb.z, p0); p1 = fmaf(win1[7], xb.w, p1);
            const float xp1 = p0 + p1;

            // Overflow publish (warp-uniform; normally skipped).
            if (nover) {
                sh[u0] = n0s; sh[u1] = n1s;
                __syncwarp();
            }

            // Recurrent gather on r (the critical chain).
            float a0 = xp0, a0b = 0.0f;
            float a1 = xp1, a1b = 0.0f;
#pragma unroll
            for (int k = 0; k < NC; ++k) {
                a0  = fmaf(v00[k], __shfl_sync(FULLMASK, r0, s00[k]), a0);
                a0b = fmaf(v01[k], __shfl_sync(FULLMASK, r1, s01[k]), a0b);
                a1  = fmaf(v10[k], __shfl_sync(FULLMASK, r0, s10[k]), a1);
                a1b = fmaf(v11[k], __shfl_sync(FULLMASK, r1, s11[k]), a1b);
            }
            float z0 = a0 + a0b;   // already scaled by 2/ln2
            float z1 = a1 + a1b;

            if (nover) {
                for (int k = 0; k < nover; ++k) {
                    const float ctr = g_ovval[k] * sh[g_ovsrc[k]];
                    const int dd = g_ovdst[k];
                    if (dd == u0) z0 += ctr;
                    if (dd == u1) z1 += ctr;
                }
                __syncwarp();
            }

            // r = rcp(exp2(z)+1); chain ex2+add+rcp (no leading mul).
            float e0, e1;
            asm("ex2.approx.f32 %0, %1;" : "=f"(e0) : "f"(z0));
            asm("ex2.approx.f32 %0, %1;" : "=f"(e1) : "f"(z1));
            asm("rcp.approx.f32 %0, %1;" : "=f"(r0) : "f"(e0 + 1.0f));
            asm("rcp.approx.f32 %0, %1;" : "=f"(r1) : "f"(e1 + 1.0f));

            // Output value n = 1 - 2r (off the critical chain).
            n0s = fmaf(-2.0f, r0, 1.0f);
            n1s = fmaf(-2.0f, r1, 1.0f);
            *optr0 = n0s;  optr0 += UNITS;
            *optr1 = n1s;  optr1 += UNITS;
        }

        // Prefetch chunk c+2 into the buffer just consumed.
        if (c + 2 < NCHUNK) {
            const float* src = inp_b + (c + 2) * CHUNK * DIN;
#pragma unroll
            for (int i = 0; i < 4; ++i) {
                int fo = lane * 16 + i * 4;
                cp_async16(&xin[buf][fo], src + fo);
            }
        }
        cp_async_commit();
    }
}

__global__ void __launch_bounds__(32)
esn_main_kernel(const float* __restrict__ inputs,
                const float* __restrict__ W_in,
                const float* __restrict__ bias,
                float* __restrict__ out) {
    const int lane = threadIdx.x;
    const int b    = blockIdx.x;

    __shared__ float xin[2][CHUNK * DIN];
    __shared__ float sh[UNITS];

    const int u0 = g_unitOf[0][lane];
    const int u1 = g_unitOf[1][lane];

    float win0[DIN], win1[DIN];
#pragma unroll
    for (int d = 0; d < DIN; ++d) {
        win0[d] = KSC * W_in[d * UNITS + u0];
        win1[d] = KSC * W_in[d * UNITS + u1];
    }
    const float b0 = KSC * bias[u0];
    const float b1 = KSC * bias[u1];

    const float* inp_b = inputs + (size_t)b * TLEN * DIN;
    float*       out_b = out    + (size_t)b * TLEN * UNITS;

    const int nover = g_nover;
    const int ncap  = g_ncap;      // warp-uniform dispatch

    if (ncap <= 1)
        time_loop<1>(lane, u0, u1, win0, win1, b0, b1, inp_b, out_b, xin, sh, nover);
    else if (ncap == 2)
        time_loop<2>(lane, u0, u1, win0, win1, b0, b1, inp_b, out_b, xin, sh, nover);
    else if (ncap == 3)
        time_loop<3>(lane, u0, u1, win0, win1, b0, b1, inp_b, out_b, xin, sh, nover);
    else
        time_loop<4>(lane, u0, u1, win0, win1, b0, b1, inp_b, out_b, xin, sh, nover);
}

extern "C" void kernel_launch(void* const* d_in, const int* in_sizes, int n_in,
                              void* d_out, int out_size) {
    const float* inputs = (const float*)d_in[0];   // [256, 4096, 8]
    const float* W_in   = (const float*)d_in[1];   // [8, 64]
    const float* bias   = (const float*)d_in[2];   // [64]
    const float* W_rec  = (const float*)d_in[3];   // [64, 64]
    float* out = (float*)d_out;                    // [256, 4096, 64]

    esn_prep_kernel<<<1, UNITS>>>(W_rec);
    esn_main_kernel<<<BATCH, 32>>>(inputs, W_in, bias, out);
}